// round 8
// baseline (speedup 1.0000x reference)
#include <cuda_runtime.h>
#include <cuda_fp16.h>
#include <math.h>
#include <stdint.h>

#define NFEAT 4096
#define BATCH 128

// ---------------- device scratch (static; no runtime allocation) -------------
__device__ float4 g_xh_raw[BATCH * NFEAT / 8];        // half [128, 4096] folded x
__device__ float4 g_act0_raw[BATCH * 2 * NFEAT / 8];  // half [128, 8192] layer0 out
__device__ float4 g_act1_raw[BATCH * 2 * NFEAT / 8];  // half [128, 8192] layer1 out
__device__ float  g_part[4 * BATCH * 2 * NFEAT];      // split-K fp32 partials (16MB)

// ---------------- closed-form fold / mask helpers ----------------------------
__device__ __forceinline__ int perm_site(int j) {
    if (j == 0) return 0;
    int m = (31 - __clz((unsigned)j)) >> 1;   // floor(log4 j)
    int q = j >> (2 * m);
    int t = j - (q << (2 * m));
    int ri = t >> m;
    int ci = t & ((1 << m) - 1);
    int s = 1 << (5 - m);
    int p = s << 1;
    int row, col;
    if (q == 1)      { row = s + ri * p; col = s + ci * p; }
    else if (q == 2) { row = s + ri * p; col = ci * p;     }
    else             { row = ri * p;     col = s + ci * p; }
    return (row << 6) + col;
}
__device__ __forceinline__ int grp_start(int j) {
    if (j == 0) return 0;
    int m = (31 - __clz((unsigned)j)) >> 1;
    return (j >> (2 * m)) << (2 * m);
}
__device__ __forceinline__ int grp_end(int j) {
    if (j == 0) return 1;
    int m = (31 - __clz((unsigned)j)) >> 1;
    return ((j >> (2 * m)) + 1) << (2 * m);
}

// ---------------- small PTX helpers -------------------------------------------
__device__ __forceinline__ uint32_t smem_u32(const void* p) {
    uint32_t a;
    asm("{ .reg .u64 t; cvta.to.shared.u64 t, %1; cvt.u32.u64 %0, t; }" : "=r"(a) : "l"(p));
    return a;
}
#define SWZ(o) ((o) ^ (((o) >> 3) & 0x70))

__device__ __forceinline__ void cp_async16(uint32_t dst, const void* src) {
    asm volatile("cp.async.cg.shared.global [%0], [%1], 16;" :: "r"(dst), "l"(src) : "memory");
}
__device__ __forceinline__ void cp_commit() {
    asm volatile("cp.async.commit_group;" ::: "memory");
}
template<int N>
__device__ __forceinline__ void cp_wait() {
    asm volatile("cp.async.wait_group %0;" :: "n"(N) : "memory");
}
__device__ __forceinline__ void ldm_x4(uint32_t addr, uint32_t& r0, uint32_t& r1,
                                       uint32_t& r2, uint32_t& r3) {
    asm volatile("ldmatrix.sync.aligned.m8n8.x4.shared.b16 {%0,%1,%2,%3}, [%4];"
                 : "=r"(r0), "=r"(r1), "=r"(r2), "=r"(r3) : "r"(addr));
}
__device__ __forceinline__ void mma16816(float* c, uint32_t a0, uint32_t a1, uint32_t a2,
                                         uint32_t a3, uint32_t b0, uint32_t b1) {
    asm volatile("mma.sync.aligned.m16n8k16.row.col.f32.f16.f16.f32 "
                 "{%0,%1,%2,%3},{%4,%5,%6,%7},{%8,%9},{%0,%1,%2,%3};"
                 : "+f"(c[0]), "+f"(c[1]), "+f"(c[2]), "+f"(c[3])
                 : "r"(a0), "r"(a1), "r"(a2), "r"(a3), "r"(b0), "r"(b1));
}

// ---------------- gather: fold input to fp16 ----------------------------------
__global__ void gather_kernel(const float* __restrict__ x) {
    int idx = blockIdx.x * blockDim.x + threadIdx.x;   // 128*4096
    int j = idx & (NFEAT - 1);
    int b = idx >> 12;
    ((half*)g_xh_raw)[idx] = __float2half_rn(x[(b << 12) + perm_site(j)]);
}

// ---------------- masked GEMM: split-K partials via mma.sync --------------------
// Partial[p][m][r] = sum_{c in K-slice, c < cut(r)} X[m,c] * W[r,c]
// M=128, N-tile=64, K-stage=64, K-slice=2048 (<=32 stages/CTA).
// Warps: 4 (m32) x 2 (n32); each warp m32 x n32 (2x4 mma frags, 32 acc regs).
// A: fp16 cp.async ring (3 x 16KB, SW128, ldmatrix).
// W: direct LDG.128 -> regs (1-stage prefetch, masked chunk skip)
//    -> mask+cvt -> 8KB fp16 H tile (single-buffered) -> ldmatrix B.
#define OFF_A 1024
#define OFF_H (OFF_A + 3 * 16384)
#define SMEM_TOTAL (OFF_H + 8192)

template<int HALVES, int SP, bool EXCL, int SEL>
__global__ __launch_bounds__(256, 2)
void mma_kernel(const float* __restrict__ W)
{
    extern __shared__ __align__(1024) char smem[];
    const uint32_t smem_base = smem_u32(smem);
    const int t = threadIdx.x;
    const int wid = t >> 5, lane = t & 31;
    const int RB = (SEL == 2) ? 64 : 128;           // 64-row blocks
    const int R  = RB * 64;
    const int C  = (SEL == 0) ? NFEAT : 2 * NFEAT;  // input features
    const int NPART = HALVES * SP;
    const int KS = NFEAT / SP;                      // K-slice within a half
    const half* Asrc = (SEL == 0) ? (const half*)g_xh_raw
                     : (SEL == 1) ? (const half*)g_act0_raw
                                  : (const half*)g_act1_raw;

    // block decode: sibling parts adjacent; long-K rowblocks first
    const int ks  = (int)blockIdx.x % NPART;
    const int rb  = RB - 1 - ((int)blockIdx.x / NPART);
    const int r0  = rb * 64;
    const int hsel = ks % HALVES;
    const int sub  = ks / HALVES;
    const int hoff = hsel * NFEAT;
    const int kst  = sub * KS;

    int* cut_s = (int*)smem;
    if (t < 64) {
        int rmod = (r0 + t) & (NFEAT - 1);
        cut_s[t] = EXCL ? grp_start(rmod) : grp_end(rmod);
    }
    __syncthreads();

    const int Kmax = cut_s[63];               // cutoffs monotone within tile
    const int span = (Kmax - kst < KS) ? (Kmax - kst) : KS;
    const int S = (span > 0) ? ((span + 63) >> 6) : 0;

    // W lane mapping: row wn (0..63), 16-float chunk wc (0..3)
    const int wn = t >> 2;
    const int wc = t & 3;
    const int wcut = cut_s[wn];
    const float* Wrow = W + (size_t)(r0 + wn) * C + hoff + kst + wc * 16;

    auto ldg_w = [&](int s, float4* wv) {
        const int k0 = kst + (s << 6) + wc * 16;
#pragma unroll
        for (int i = 0; i < 4; i++) {
            if (k0 + i * 4 < wcut)
                wv[i] = __ldg((const float4*)(Wrow + (s << 6) + i * 4));
            else
                wv[i] = make_float4(0.f, 0.f, 0.f, 0.f);
        }
    };

    auto produce_a = [&](int s) {
        if (s < S) {
            const int k0 = kst + (s << 6);
            const half* Ah = Asrc + hoff + k0;
            uint32_t Ab = smem_base + OFF_A + (s % 3) * 16384;
#pragma unroll
            for (int l = 0; l < 4; l++) {
                int fid = t + l * 256;
                int m = fid >> 3, c16 = fid & 7;
                cp_async16(Ab + SWZ(m * 128 + c16 * 16), Ah + (size_t)m * C + c16 * 8);
            }
        }
        cp_commit();   // dummy groups keep wait-count invariant
    };

    float acc[2][4][4];
#pragma unroll
    for (int i = 0; i < 2; i++)
#pragma unroll
        for (int j = 0; j < 4; j++)
#pragma unroll
            for (int k = 0; k < 4; k++) acc[i][j][k] = 0.f;

    const int mw = wid & 3, nw = wid >> 2;
    const int rowA0 = mw * 32 + (lane & 15);
    const int rowB0 = nw * 32 + (lane & 15);
    const int colHi = (lane >> 4) * 8;
    const int klane = (lane & 3) * 2;

    float4 wv[4];
    if (S > 0) ldg_w(0, wv);
    produce_a(0);
    produce_a(1);

    for (int s = 0; s < S; s++) {
        cp_wait<1>();
        __syncthreads();          // A[s] ready; all warps done reading H[s-1]

        // ---- convert W regs (stage s) -> fp16 H tile, per-element mask
        {
            const int k0 = kst + (s << 6) + wc * 16;
            half2 h[8];
#pragma unroll
            for (int i = 0; i < 4; i++) {
                float xa = (k0 + i * 4 + 0 < wcut) ? wv[i].x : 0.f;
                float xb = (k0 + i * 4 + 1 < wcut) ? wv[i].y : 0.f;
                float xc = (k0 + i * 4 + 2 < wcut) ? wv[i].z : 0.f;
                float xd = (k0 + i * 4 + 3 < wcut) ? wv[i].w : 0.f;
                h[i * 2 + 0] = __floats2half2_rn(xa, xb);
                h[i * 2 + 1] = __floats2half2_rn(xc, xd);
            }
            uint4 pk0, pk1;
            pk0.x = *(uint32_t*)&h[0]; pk0.y = *(uint32_t*)&h[1];
            pk0.z = *(uint32_t*)&h[2]; pk0.w = *(uint32_t*)&h[3];
            pk1.x = *(uint32_t*)&h[4]; pk1.y = *(uint32_t*)&h[5];
            pk1.z = *(uint32_t*)&h[6]; pk1.w = *(uint32_t*)&h[7];
            *(uint4*)(smem + OFF_H + SWZ(wn * 128 + wc * 32)) = pk0;
            *(uint4*)(smem + OFF_H + SWZ(wn * 128 + wc * 32 + 16)) = pk1;
        }
        __syncthreads();          // H ready

        produce_a(s + 2);
        if (s + 1 < S) ldg_w(s + 1, wv);   // prefetch next W during compute

        const uint32_t Ab = smem_base + OFF_A + (s % 3) * 16384;
        const uint32_t Hb = smem_base + OFF_H;
#pragma unroll
        for (int kk = 0; kk < 4; kk++) {
            const int kc = kk * 16 + colHi;
            uint32_t a0[4], a1[4];
            ldm_x4(Ab + SWZ(rowA0 * 128 + kc * 2), a0[0], a0[1], a0[2], a0[3]);
            ldm_x4(Ab + SWZ((rowA0 + 16) * 128 + kc * 2), a1[0], a1[1], a1[2], a1[3]);
#pragma unroll
            for (int nj = 0; nj < 2; nj++) {
                uint32_t p0, p1, p2, p3;
                ldm_x4(Hb + SWZ((rowB0 + nj * 16) * 128 + kc * 2), p0, p1, p2, p3);
                mma16816(acc[0][nj * 2 + 0], a0[0], a0[1], a0[2], a0[3], p0, p2);
                mma16816(acc[0][nj * 2 + 1], a0[0], a0[1], a0[2], a0[3], p1, p3);
                mma16816(acc[1][nj * 2 + 0], a1[0], a1[1], a1[2], a1[3], p0, p2);
                mma16816(acc[1][nj * 2 + 1], a1[0], a1[1], a1[2], a1[3], p1, p3);
            }
        }
    }

    // ---- epilogue: fp32 partial store
    float* part = g_part + (size_t)ks * (BATCH * 2 * NFEAT);
    const int mrow = lane >> 2;
#pragma unroll
    for (int i = 0; i < 2; i++) {
        const int m = mw * 32 + i * 16 + mrow;
#pragma unroll
        for (int j = 0; j < 4; j++) {
            const int r = r0 + nw * 32 + (j >> 1) * 16 + (j & 1) * 8 + klane;
            *(float2*)(part + (size_t)m * R + r) = make_float2(acc[i][j][0], acc[i][j][1]);
            *(float2*)(part + (size_t)(m + 8) * R + r) = make_float2(acc[i][j][2], acc[i][j][3]);
        }
    }
}

// ---------------- reduce: sum parts + bias + PReLU -> fp16 activations ---------
template<int SEL, int NP>
__global__ void reduce_prelu_kernel(const float* __restrict__ bias,
                                    const float* __restrict__ alpha)
{
    const int idx4 = (blockIdx.x * blockDim.x + threadIdx.x) * 4;  // over 128*8192
    const int r = idx4 & (2 * NFEAT - 1);
    float4 v = *(const float4*)(g_part + idx4);
#pragma unroll
    for (int p = 1; p < NP; p++) {
        float4 u = *(const float4*)(g_part + (size_t)p * (BATCH * 2 * NFEAT) + idx4);
        v.x += u.x; v.y += u.y; v.z += u.z; v.w += u.w;
    }
    const float4 bv = *(const float4*)(bias + r);
    const float4 av = *(const float4*)(alpha + r);
    v.x += bv.x; v.y += bv.y; v.z += bv.z; v.w += bv.w;
    v.x = (v.x > 0.f) ? v.x : av.x * v.x;
    v.y = (v.y > 0.f) ? v.y : av.y * v.y;
    v.z = (v.z > 0.f) ? v.z : av.z * v.z;
    v.w = (v.w > 0.f) ? v.w : av.w * v.w;
    half2 lo = __floats2half2_rn(v.x, v.y);
    half2 hi = __floats2half2_rn(v.z, v.w);
    uint2 pk;
    pk.x = *(uint32_t*)&lo; pk.y = *(uint32_t*)&hi;
    half* act = (SEL == 0) ? (half*)g_act0_raw : (half*)g_act1_raw;
    *(uint2*)(act + idx4) = pk;
}

// ---------------- L2 final: sum parts + bias, sigmoid, unfold scatter ----------
__global__ void l2_final_kernel(const float* __restrict__ bias, float* __restrict__ out) {
    int idx = blockIdx.x * blockDim.x + threadIdx.x;   // 128*4096
    int r = idx & (NFEAT - 1);
    int m = idx >> 12;
    float v = g_part[idx]
            + g_part[(size_t)1 * (BATCH * 2 * NFEAT) + idx]
            + g_part[(size_t)2 * (BATCH * 2 * NFEAT) + idx]
            + g_part[(size_t)3 * (BATCH * 2 * NFEAT) + idx]
            + __ldg(bias + r);
    float g = (r == 0) ? 0.5f : 1.f / (1.f + __expf(-v));
    out[(m << 12) + perm_site(r)] = g;
}

// ---------------- launcher ------------------------------------------------------
extern "C" void kernel_launch(void* const* d_in, const int* in_sizes, int n_in,
                              void* d_out, int out_size) {
    const float* x  = (const float*)d_in[0];
    const float* W0 = (const float*)d_in[1];
    const float* b0 = (const float*)d_in[2];
    const float* a1 = (const float*)d_in[3];
    const float* W1 = (const float*)d_in[4];
    const float* b1 = (const float*)d_in[5];
    const float* a2 = (const float*)d_in[6];
    const float* W2 = (const float*)d_in[7];
    const float* b2 = (const float*)d_in[8];
    float* out = (float*)d_out;

    cudaFuncSetAttribute(mma_kernel<1, 2, true,  0>, cudaFuncAttributeMaxDynamicSharedMemorySize, SMEM_TOTAL);
    cudaFuncSetAttribute(mma_kernel<2, 2, false, 1>, cudaFuncAttributeMaxDynamicSharedMemorySize, SMEM_TOTAL);
    cudaFuncSetAttribute(mma_kernel<2, 2, false, 2>, cudaFuncAttributeMaxDynamicSharedMemorySize, SMEM_TOTAL);

    gather_kernel<<<(BATCH * NFEAT) / 256, 256>>>(x);

    // L0: exclusive mask, C=4096 split into 2x2048 -> 2 partials
    mma_kernel<1, 2, true,  0><<<128 * 2, 256, SMEM_TOTAL>>>(W0);
    reduce_prelu_kernel<0, 2><<<(BATCH * 2 * NFEAT) / 1024, 256>>>(b0, a1);
    // L1: inclusive mask, C=8192 split into 4x2048 -> 4 partials
    mma_kernel<2, 2, false, 1><<<128 * 4, 256, SMEM_TOTAL>>>(W1);
    reduce_prelu_kernel<1, 4><<<(BATCH * 2 * NFEAT) / 1024, 256>>>(b1, a2);
    // L2: inclusive mask, C=8192 split into 4x2048 -> 4 partials
    mma_kernel<2, 2, false, 2><<<64 * 4, 256, SMEM_TOTAL>>>(W2);
    // L2 reduce: sum + bias, sigmoid, xhat mask/bias, unfold scatter
    l2_final_kernel<<<(BATCH * NFEAT) / 256, 256>>>(b2, out);
}

// round 9
// speedup vs baseline: 1.1432x; 1.1432x over previous
#include <cuda_runtime.h>
#include <cuda_fp16.h>
#include <math.h>
#include <stdint.h>

#define NFEAT 4096
#define BATCH 128

// ---------------- device scratch (static; no runtime allocation) -------------
__device__ float4 g_xh_raw[BATCH * NFEAT / 8];        // half [128, 4096] folded x
__device__ float4 g_act0_raw[BATCH * 2 * NFEAT / 8];  // half [128, 8192] layer0 out
__device__ float4 g_act1_raw[BATCH * 2 * NFEAT / 8];  // half [128, 8192] layer1 out
__device__ float  g_part[4 * BATCH * 2 * NFEAT];      // split-K fp32 partials (16MB)

// ---------------- closed-form fold / mask helpers ----------------------------
__device__ __forceinline__ int perm_site(int j) {
    if (j == 0) return 0;
    int m = (31 - __clz((unsigned)j)) >> 1;   // floor(log4 j)
    int q = j >> (2 * m);
    int t = j - (q << (2 * m));
    int ri = t >> m;
    int ci = t & ((1 << m) - 1);
    int s = 1 << (5 - m);
    int p = s << 1;
    int row, col;
    if (q == 1)      { row = s + ri * p; col = s + ci * p; }
    else if (q == 2) { row = s + ri * p; col = ci * p;     }
    else             { row = ri * p;     col = s + ci * p; }
    return (row << 6) + col;
}
__device__ __forceinline__ int grp_start(int j) {
    if (j == 0) return 0;
    int m = (31 - __clz((unsigned)j)) >> 1;
    return (j >> (2 * m)) << (2 * m);
}
__device__ __forceinline__ int grp_end(int j) {
    if (j == 0) return 1;
    int m = (31 - __clz((unsigned)j)) >> 1;
    return ((j >> (2 * m)) + 1) << (2 * m);
}

// ---------------- small PTX helpers -------------------------------------------
__device__ __forceinline__ uint32_t smem_u32(const void* p) {
    uint32_t a;
    asm("{ .reg .u64 t; cvta.to.shared.u64 t, %1; cvt.u32.u64 %0, t; }" : "=r"(a) : "l"(p));
    return a;
}
#define SWZ(o) ((o) ^ (((o) >> 3) & 0x70))

__device__ __forceinline__ void cp_async16(uint32_t dst, const void* src) {
    asm volatile("cp.async.cg.shared.global [%0], [%1], 16;" :: "r"(dst), "l"(src) : "memory");
}
__device__ __forceinline__ void cp_commit() {
    asm volatile("cp.async.commit_group;" ::: "memory");
}
template<int N>
__device__ __forceinline__ void cp_wait() {
    asm volatile("cp.async.wait_group %0;" :: "n"(N) : "memory");
}
__device__ __forceinline__ void ldm_x4(uint32_t addr, uint32_t& r0, uint32_t& r1,
                                       uint32_t& r2, uint32_t& r3) {
    asm volatile("ldmatrix.sync.aligned.m8n8.x4.shared.b16 {%0,%1,%2,%3}, [%4];"
                 : "=r"(r0), "=r"(r1), "=r"(r2), "=r"(r3) : "r"(addr));
}
__device__ __forceinline__ void mma16816(float* c, uint32_t a0, uint32_t a1, uint32_t a2,
                                         uint32_t a3, uint32_t b0, uint32_t b1) {
    asm volatile("mma.sync.aligned.m16n8k16.row.col.f32.f16.f16.f32 "
                 "{%0,%1,%2,%3},{%4,%5,%6,%7},{%8,%9},{%0,%1,%2,%3};"
                 : "+f"(c[0]), "+f"(c[1]), "+f"(c[2]), "+f"(c[3])
                 : "r"(a0), "r"(a1), "r"(a2), "r"(a3), "r"(b0), "r"(b1));
}

// ---------------- gather: fold input to fp16 ----------------------------------
__global__ void gather_kernel(const float* __restrict__ x) {
    int idx = blockIdx.x * blockDim.x + threadIdx.x;   // 128*4096
    int j = idx & (NFEAT - 1);
    int b = idx >> 12;
    ((half*)g_xh_raw)[idx] = __float2half_rn(x[(b << 12) + perm_site(j)]);
}

// ---------------- masked GEMM: split-K partials via mma.sync --------------------
// Partial[p][m][r] = sum_{c in this CTA's K-slice, c < cut(r)} X[m,c] * W[r,c]
// M=128 (batch), N-tile=32, K-stage=64, K-slice=2048 (<=32 stages per CTA).
// A: fp16 cp.async ring (3 x 16KB, SW128, ldmatrix).
// W: fp32 cp.async ring (2 x 8.5KB) -> coop mask+cvt -> H fp16 tile (2 x 4KB)
// Single __syncthreads per stage:
//   cp_wait -> convert W[s]->H[s&1] -> sync -> produce(s+2) -> MMA(A[s%3], H[s&1])
#define OFF_A 1024
#define OFF_W (OFF_A + 3 * 16384)
#define OFF_H (OFF_W + 2 * 8704)
#define W_STRIDE 272                       /* 68 floats per n-row */
#define SMEM_TOTAL (OFF_H + 2 * 4096)

template<int HALVES, int SP, bool EXCL, int SEL>
__global__ __launch_bounds__(256, 3)
void mma_kernel(const float* __restrict__ W)
{
    extern __shared__ __align__(1024) char smem[];
    const uint32_t smem_base = smem_u32(smem);
    const int t = threadIdx.x;
    const int wid = t >> 5, lane = t & 31;
    const int RB = (SEL == 2) ? 128 : 256;          // 32-row blocks
    const int R  = RB * 32;
    const int C  = (SEL == 0) ? NFEAT : 2 * NFEAT;  // input features
    const int NPART = HALVES * SP;
    const int KS = NFEAT / SP;                      // K-slice within a half
    const half* Asrc = (SEL == 0) ? (const half*)g_xh_raw
                     : (SEL == 1) ? (const half*)g_act0_raw
                                  : (const half*)g_act1_raw;

    // block decode: sibling parts adjacent; long-K rowblocks first
    const int ks  = (int)blockIdx.x % NPART;
    const int rb  = RB - 1 - ((int)blockIdx.x / NPART);
    const int r0  = rb * 32;
    const int hsel = ks % HALVES;
    const int sub  = ks / HALVES;
    const int hoff = hsel * NFEAT;
    const int kst  = sub * KS;

    int* cut_s = (int*)smem;
    if (t < 32) {
        int rmod = (r0 + t) & (NFEAT - 1);
        cut_s[t] = EXCL ? grp_start(rmod) : grp_end(rmod);
    }
    __syncthreads();

    const int Kmax = cut_s[31];               // cutoffs monotone within tile
    const int span = (Kmax - kst < KS) ? (Kmax - kst) : KS;
    const int S = (span > 0) ? ((span + 63) >> 6) : 0;

    // producer lane mapping for W: n-row + two 16B chunks per thread
    const int wn = t >> 3;                    // 0..31
    const int wc = t & 7;                     // chunk base (also +8)
    const int wcut = cut_s[wn];

    auto produce = [&](int s) {
        if (s < S) {
            const int k0 = kst + (s << 6);
            const int buf = s % 3;
            // A tile 128 x 64 fp16
            const half* Ah = Asrc + hoff + k0;
            uint32_t Ab = smem_base + OFF_A + buf * 16384;
#pragma unroll
            for (int l = 0; l < 4; l++) {
                int fid = t + l * 256;
                int m = fid >> 3, c16 = fid & 7;
                cp_async16(Ab + SWZ(m * 128 + c16 * 16), Ah + (size_t)m * C + c16 * 8);
            }
            // W tile 32 x 64 fp32 (masked chunk skip), 2-deep ring
            uint32_t Wb = smem_base + OFF_W + (s & 1) * 8704;
            const float* Wrow = W + (size_t)(r0 + wn) * C + hoff + k0;
#pragma unroll
            for (int l = 0; l < 2; l++) {
                int cc = wc + l * 8;
                if (k0 + cc * 4 < wcut)
                    cp_async16(Wb + wn * W_STRIDE + cc * 16, Wrow + cc * 4);
            }
        }
        cp_commit();   // always commit (dummy groups keep wait-count invariant)
    };

    float acc[4][4];
#pragma unroll
    for (int i = 0; i < 4; i++)
#pragma unroll
        for (int j = 0; j < 4; j++) acc[i][j] = 0.f;

    const int rowA = wid * 16 + (lane & 15);
    const int rowB = lane & 15;
    const int colHi = (lane >> 4) * 8;
    const int klane = (lane & 3) * 2;

    produce(0);
    produce(1);

    for (int s = 0; s < S; s++) {
        cp_wait<1>();          // A[s], W[s] arrived

        const int k0 = kst + (s << 6);
        const uint32_t Hoff = OFF_H + (s & 1) * 4096;

        // ---- cooperative mask + fp32->fp16 convert (each element once)
        // H[s&1] was last read by MMA[s-2], ordered before sync(s-1): safe.
        {
            const float* Wf = (const float*)(smem + OFF_W + (s & 1) * 8704);
            const float* p = Wf + wn * 68 + wc * 8;
            float4 u0 = *(const float4*)(p);
            float4 u1 = *(const float4*)(p + 4);
            const int ke = k0 + wc * 8;
            half2 h0 = __floats2half2_rn((ke     < wcut) ? u0.x : 0.f,
                                         (ke + 1 < wcut) ? u0.y : 0.f);
            half2 h1 = __floats2half2_rn((ke + 2 < wcut) ? u0.z : 0.f,
                                         (ke + 3 < wcut) ? u0.w : 0.f);
            half2 h2 = __floats2half2_rn((ke + 4 < wcut) ? u1.x : 0.f,
                                         (ke + 5 < wcut) ? u1.y : 0.f);
            half2 h3 = __floats2half2_rn((ke + 6 < wcut) ? u1.z : 0.f,
                                         (ke + 7 < wcut) ? u1.w : 0.f);
            uint4 pk;
            pk.x = *(uint32_t*)&h0; pk.y = *(uint32_t*)&h1;
            pk.z = *(uint32_t*)&h2; pk.w = *(uint32_t*)&h3;
            *(uint4*)(smem + Hoff + SWZ(wn * 128 + wc * 16)) = pk;
        }
        __syncthreads();       // H[s] visible; all MMA[s-1] + convert reads done

        produce(s + 2);        // writes A[(s-1)%3], W[s&1] -- both safe post-sync

        const uint32_t Ab = smem_base + OFF_A + (s % 3) * 16384;
        const uint32_t Hb = smem_base + Hoff;
#pragma unroll
        for (int kk = 0; kk < 4; kk++) {
            const int kc = kk * 16 + colHi;
            uint32_t a0, a1, a2, a3, p0, p1, p2, p3, q0, q1, q2, q3;
            ldm_x4(Ab + SWZ(rowA * 128 + kc * 2), a0, a1, a2, a3);
            ldm_x4(Hb + SWZ(rowB * 128 + kc * 2), p0, p1, p2, p3);
            ldm_x4(Hb + SWZ((rowB + 16) * 128 + kc * 2), q0, q1, q2, q3);
            mma16816(acc[0], a0, a1, a2, a3, p0, p2);
            mma16816(acc[1], a0, a1, a2, a3, p1, p3);
            mma16816(acc[2], a0, a1, a2, a3, q0, q2);
            mma16816(acc[3], a0, a1, a2, a3, q1, q3);
        }
    }

    // ---- epilogue: fp32 partial store
    float* part = g_part + (size_t)ks * (BATCH * 2 * NFEAT);
    const int m = wid * 16 + (lane >> 2);      // rows m and m+8
#pragma unroll
    for (int ni = 0; ni < 4; ni++) {
        int r = r0 + ni * 8 + klane;
        *(float2*)(part + (size_t)m * R + r) = make_float2(acc[ni][0], acc[ni][1]);
        *(float2*)(part + (size_t)(m + 8) * R + r) = make_float2(acc[ni][2], acc[ni][3]);
    }
}

// ---------------- reduce: sum parts + bias + PReLU -> fp16 activations ---------
template<int SEL, int NP>
__global__ void reduce_prelu_kernel(const float* __restrict__ bias,
                                    const float* __restrict__ alpha)
{
    const int idx4 = (blockIdx.x * blockDim.x + threadIdx.x) * 4;  // over 128*8192
    const int r = idx4 & (2 * NFEAT - 1);
    float4 v = *(const float4*)(g_part + idx4);
#pragma unroll
    for (int p = 1; p < NP; p++) {
        float4 u = *(const float4*)(g_part + (size_t)p * (BATCH * 2 * NFEAT) + idx4);
        v.x += u.x; v.y += u.y; v.z += u.z; v.w += u.w;
    }
    const float4 bv = *(const float4*)(bias + r);
    const float4 av = *(const float4*)(alpha + r);
    v.x += bv.x; v.y += bv.y; v.z += bv.z; v.w += bv.w;
    v.x = (v.x > 0.f) ? v.x : av.x * v.x;
    v.y = (v.y > 0.f) ? v.y : av.y * v.y;
    v.z = (v.z > 0.f) ? v.z : av.z * v.z;
    v.w = (v.w > 0.f) ? v.w : av.w * v.w;
    half2 lo = __floats2half2_rn(v.x, v.y);
    half2 hi = __floats2half2_rn(v.z, v.w);
    uint2 pk;
    pk.x = *(uint32_t*)&lo; pk.y = *(uint32_t*)&hi;
    half* act = (SEL == 0) ? (half*)g_act0_raw : (half*)g_act1_raw;
    *(uint2*)(act + idx4) = pk;
}

// ---------------- L2 final: sum parts + bias, sigmoid, unfold scatter ----------
__global__ void l2_final_kernel(const float* __restrict__ bias, float* __restrict__ out) {
    int idx = blockIdx.x * blockDim.x + threadIdx.x;   // 128*4096
    int r = idx & (NFEAT - 1);
    int m = idx >> 12;
    float v = g_part[idx]
            + g_part[(size_t)1 * (BATCH * 2 * NFEAT) + idx]
            + g_part[(size_t)2 * (BATCH * 2 * NFEAT) + idx]
            + g_part[(size_t)3 * (BATCH * 2 * NFEAT) + idx]
            + __ldg(bias + r);
    float g = (r == 0) ? 0.5f : 1.f / (1.f + __expf(-v));
    out[(m << 12) + perm_site(r)] = g;
}

// ---------------- launcher ------------------------------------------------------
extern "C" void kernel_launch(void* const* d_in, const int* in_sizes, int n_in,
                              void* d_out, int out_size) {
    const float* x  = (const float*)d_in[0];
    const float* W0 = (const float*)d_in[1];
    const float* b0 = (const float*)d_in[2];
    const float* a1 = (const float*)d_in[3];
    const float* W1 = (const float*)d_in[4];
    const float* b1 = (const float*)d_in[5];
    const float* a2 = (const float*)d_in[6];
    const float* W2 = (const float*)d_in[7];
    const float* b2 = (const float*)d_in[8];
    float* out = (float*)d_out;

    cudaFuncSetAttribute(mma_kernel<1, 2, true,  0>, cudaFuncAttributeMaxDynamicSharedMemorySize, SMEM_TOTAL);
    cudaFuncSetAttribute(mma_kernel<2, 2, false, 1>, cudaFuncAttributeMaxDynamicSharedMemorySize, SMEM_TOTAL);
    cudaFuncSetAttribute(mma_kernel<2, 2, false, 2>, cudaFuncAttributeMaxDynamicSharedMemorySize, SMEM_TOTAL);

    gather_kernel<<<(BATCH * NFEAT) / 256, 256>>>(x);

    // L0: exclusive mask, C=4096 split into 2x2048 -> 2 partials
    mma_kernel<1, 2, true,  0><<<512, 256, SMEM_TOTAL>>>(W0);
    reduce_prelu_kernel<0, 2><<<(BATCH * 2 * NFEAT) / 1024, 256>>>(b0, a1);
    // L1: inclusive mask, C=8192 split into 4x2048 -> 4 partials
    mma_kernel<2, 2, false, 1><<<1024, 256, SMEM_TOTAL>>>(W1);
    reduce_prelu_kernel<1, 4><<<(BATCH * 2 * NFEAT) / 1024, 256>>>(b1, a2);
    // L2: inclusive mask, C=8192 split into 4x2048 -> 4 partials
    mma_kernel<2, 2, false, 2><<<512, 256, SMEM_TOTAL>>>(W2);
    // L2 reduce: sum + bias, sigmoid, xhat mask/bias, unfold scatter
    l2_final_kernel<<<(BATCH * NFEAT) / 256, 256>>>(b2, out);
}